// round 6
// baseline (speedup 1.0000x reference)
#include <cuda_runtime.h>
#include <math.h>

#define BATCH 4
#define SEQL  2048
#define DIM   768
#define NST   16
#define BL    (BATCH*SEQL)
#define NCH   64
#define CL    (SEQL/NCH)   // 32

#define TL 64              // proj tile = 2 chunks
#define KC 32
#define LOG2E 1.4426950408889634f

// scratch (static device globals — no runtime allocation)
__device__ float g_delta[BL];
__device__ float g_sdelta[BATCH*NCH];
__device__ float g_Bt[BL*NST];   // [pos][n]
__device__ float g_Ct[BL*NST];   // [pos][n]
__device__ float g_xend [BATCH*DIM*NCH*NST];  // [(b*DIM+d)*NCH + c][n]
__device__ float g_xinit[BATCH*DIM*NCH*NST];

__device__ __forceinline__ float ex2f(float x) {
    float y;
    asm("ex2.approx.ftz.f32 %0, %1;" : "=f"(y) : "f"(x));
    return y;
}

// ---- kernel 1: proj + fused delta/softplus + chunk delta-sums ---------------
__global__ void proj_kernel(const float* __restrict__ u,
                            const float* __restrict__ W_B,
                            const float* __restrict__ W_C,
                            const float* __restrict__ q_delta,
                            const float* __restrict__ p_delta) {
    __shared__ __align__(16) float Us[KC*68];
    __shared__ __align__(16) float Ws[KC*36];   // cols 0..31 = W rows, col 32 = q_delta
    __shared__ __align__(16) float Bo[TL*NST];
    __shared__ __align__(16) float Co[TL*NST];
    int t  = threadIdx.x;       // 128 threads
    int tx = t & 15;
    int ty = t >> 4;
    int blb = blockIdx.x * TL;

    float acc[4][4];
    float dacc[4] = {0.f, 0.f, 0.f, 0.f};
#pragma unroll
    for (int a = 0; a < 4; a++)
#pragma unroll
        for (int c = 0; c < 4; c++) acc[a][c] = 0.f;

    for (int dc = 0; dc < DIM; dc += KC) {
#pragma unroll
        for (int it = 0; it < (TL*KC)/128; it++) {
            int idx = t + it*128;
            int k = idx & 31, p = idx >> 5;
            Us[k*68 + p] = u[(size_t)(blb + p)*DIM + dc + k];
        }
#pragma unroll
        for (int it = 0; it < (32*KC)/128; it++) {
            int idx = t + it*128;
            int k = idx & 31, j = idx >> 5;
            const float* wr = (j < 16) ? (W_B + j*DIM) : (W_C + (j-16)*DIM);
            Ws[k*36 + j] = wr[dc + k];
        }
        if (t < 32) Ws[t*36 + 32] = q_delta[dc + t];
        __syncthreads();
#pragma unroll
        for (int k = 0; k < KC; k++) {
            float4 u4 = *(const float4*)(Us + k*68 + tx*4);
            float4 w4 = *(const float4*)(Ws + k*36 + ty*4);
            float us[4] = {u4.x, u4.y, u4.z, u4.w};
            float ws4[4] = {w4.x, w4.y, w4.z, w4.w};
#pragma unroll
            for (int a = 0; a < 4; a++)
#pragma unroll
                for (int c = 0; c < 4; c++)
                    acc[a][c] = fmaf(ws4[a], us[c], acc[a][c]);
            if (ty == 0) {
                float qk = Ws[k*36 + 32];
#pragma unroll
                for (int c = 0; c < 4; c++)
                    dacc[c] = fmaf(qk, us[c], dacc[c]);
            }
        }
        __syncthreads();
    }
    // delta epilogue — lanes 0..15 of warp 0; tx 0-7 = chunk 2*bx, tx 8-15 = chunk 2*bx+1
    if (ty == 0) {
        float p0 = p_delta[0];
        float s = 0.f;
#pragma unroll
        for (int c = 0; c < 4; c++) {
            float z = dacc[c] + p0;
            float sp = (z > 20.f) ? z : log1pf(__expf(z));
            g_delta[blb + tx*4 + c] = sp;
            s += sp;
        }
        // 8-lane sub-reductions (groups {0-7},{8-15} stay independent: offsets < 8)
        s += __shfl_xor_sync(0xffffu, s, 4);
        s += __shfl_xor_sync(0xffffu, s, 2);
        s += __shfl_xor_sync(0xffffu, s, 1);
        if (tx == 0) g_sdelta[blockIdx.x*2]     = s;
        if (tx == 8) g_sdelta[blockIdx.x*2 + 1] = s;
    }
    // transpose B/C through smem to [pos][n]
#pragma unroll
    for (int a = 0; a < 4; a++) {
        int j = ty*4 + a;
        float* o = (j < 16) ? Bo : Co;
        int jj = j & 15;
#pragma unroll
        for (int c = 0; c < 4; c++)
            o[(tx*4 + c)*NST + jj] = acc[a][c];
    }
    __syncthreads();
#pragma unroll
    for (int it = 0; it < (TL*NST)/(128*4); it++) {
        int i = (t + it*128)*4;
        *(float4*)(g_Bt + (size_t)blb*NST + i) = *(const float4*)(Bo + i);
        *(float4*)(g_Ct + (size_t)blb*NST + i) = *(const float4*)(Co + i);
    }
}

// ---- kernel 2: local chunk scans (x0 = 0) -> x_end --------------------------
__global__ void __launch_bounds__(128) scan_init_kernel(const float* __restrict__ u,
                                                        const float* __restrict__ A) {
    __shared__ float ds[CL];
    __shared__ __align__(16) float Bs[CL*NST];
    int t = threadIdx.x;
    int b = blockIdx.z, c = blockIdx.y;
    int d = blockIdx.x * 128 + t;
    int pos0 = b*SEQL + c*CL;

    if (t < CL) ds[t] = g_delta[pos0 + t];
#pragma unroll
    for (int i = t; i < CL*NST/4; i += 128)
        *(float4*)(Bs + i*4) = *(const float4*)(g_Bt + (size_t)pos0*NST + i*4);
    __syncthreads();

    float A2[NST];
#pragma unroll
    for (int k = 0; k < 4; k++) {
        float4 a4 = *(const float4*)(A + d*NST + k*4);
        A2[k*4+0] = a4.x*LOG2E; A2[k*4+1] = a4.y*LOG2E;
        A2[k*4+2] = a4.z*LOG2E; A2[k*4+3] = a4.w*LOG2E;
    }
    float x[NST];
#pragma unroll
    for (int k = 0; k < NST; k++) x[k] = 0.f;

    const float* up = u + (size_t)pos0*DIM + d;
#pragma unroll 4
    for (int l = 0; l < CL; l++) {
        float dl = ds[l];
        float du = dl * up[(size_t)l*DIM];
        const float4* bp = (const float4*)(Bs + l*NST);
#pragma unroll
        for (int k = 0; k < 4; k++) {
            float4 b4 = bp[k];
            x[k*4+0] = fmaf(ex2f(dl*A2[k*4+0]), x[k*4+0], du*b4.x);
            x[k*4+1] = fmaf(ex2f(dl*A2[k*4+1]), x[k*4+1], du*b4.y);
            x[k*4+2] = fmaf(ex2f(dl*A2[k*4+2]), x[k*4+2], du*b4.z);
            x[k*4+3] = fmaf(ex2f(dl*A2[k*4+3]), x[k*4+3], du*b4.w);
        }
    }
    float* xe = g_xend + (((size_t)b*DIM + d)*NCH + c)*NST;
#pragma unroll
    for (int k = 0; k < 4; k++)
        *(float4*)(xe + k*4) = make_float4(x[k*4], x[k*4+1], x[k*4+2], x[k*4+3]);
}

// ---- kernel 3: serial chain over chunks -> x_init ---------------------------
__global__ void chain_kernel(const float* __restrict__ A) {
    int t = blockIdx.x * blockDim.x + threadIdx.x;   // (b*DIM+d)*NST + n
    int n = t & 15;
    int bd = t >> 4;
    int b = bd / DIM;
    int d = bd - b*DIM;
    float A2 = A[d*NST + n] * LOG2E;
    float x = 0.f;
#pragma unroll
    for (int c = 0; c < NCH; c++) {
        size_t idx = ((size_t)bd*NCH + c)*NST + n;
        g_xinit[idx] = x;
        float P = ex2f(A2 * g_sdelta[b*NCH + c]);
        x = fmaf(P, x, g_xend[idx]);
    }
}

// ---- kernel 4: main scan with correct init, emit y --------------------------
__global__ void __launch_bounds__(128) scan_main_kernel(const float* __restrict__ u,
                                                        const float* __restrict__ A,
                                                        float* __restrict__ y) {
    __shared__ float ds[CL];
    __shared__ __align__(16) float Bs[CL*NST];
    __shared__ __align__(16) float Cs[CL*NST];
    int t = threadIdx.x;
    int b = blockIdx.z, c = blockIdx.y;
    int d = blockIdx.x * 128 + t;
    int pos0 = b*SEQL + c*CL;

    if (t < CL) ds[t] = g_delta[pos0 + t];
#pragma unroll
    for (int i = t; i < CL*NST/4; i += 128) {
        *(float4*)(Bs + i*4) = *(const float4*)(g_Bt + (size_t)pos0*NST + i*4);
        *(float4*)(Cs + i*4) = *(const float4*)(g_Ct + (size_t)pos0*NST + i*4);
    }
    __syncthreads();

    float A2[NST];
#pragma unroll
    for (int k = 0; k < 4; k++) {
        float4 a4 = *(const float4*)(A + d*NST + k*4);
        A2[k*4+0] = a4.x*LOG2E; A2[k*4+1] = a4.y*LOG2E;
        A2[k*4+2] = a4.z*LOG2E; A2[k*4+3] = a4.w*LOG2E;
    }
    float x[NST];
    const float* xi = g_xinit + (((size_t)b*DIM + d)*NCH + c)*NST;
#pragma unroll
    for (int k = 0; k < 4; k++) {
        float4 v = *(const float4*)(xi + k*4);
        x[k*4] = v.x; x[k*4+1] = v.y; x[k*4+2] = v.z; x[k*4+3] = v.w;
    }

    const float* up = u + (size_t)pos0*DIM + d;
    float*       yp = y + (size_t)pos0*DIM + d;
#pragma unroll 4
    for (int l = 0; l < CL; l++) {
        float dl = ds[l];
        float du = dl * up[(size_t)l*DIM];
        const float4* bp = (const float4*)(Bs + l*NST);
        const float4* cp = (const float4*)(Cs + l*NST);
        float acc = 0.f;
#pragma unroll
        for (int k = 0; k < 4; k++) {
            float4 b4 = bp[k];
            float4 c4 = cp[k];
            x[k*4+0] = fmaf(ex2f(dl*A2[k*4+0]), x[k*4+0], du*b4.x);
            x[k*4+1] = fmaf(ex2f(dl*A2[k*4+1]), x[k*4+1], du*b4.y);
            x[k*4+2] = fmaf(ex2f(dl*A2[k*4+2]), x[k*4+2], du*b4.z);
            x[k*4+3] = fmaf(ex2f(dl*A2[k*4+3]), x[k*4+3], du*b4.w);
            acc = fmaf(x[k*4+0], c4.x, acc);
            acc = fmaf(x[k*4+1], c4.y, acc);
            acc = fmaf(x[k*4+2], c4.z, acc);
            acc = fmaf(x[k*4+3], c4.w, acc);
        }
        yp[(size_t)l*DIM] = acc;
    }
}

extern "C" void kernel_launch(void* const* d_in, const int* in_sizes, int n_in,
                              void* d_out, int out_size) {
    const float* u       = (const float*)d_in[0];
    const float* A       = (const float*)d_in[1];
    const float* W_B     = (const float*)d_in[2];
    const float* W_C     = (const float*)d_in[3];
    const float* q_delta = (const float*)d_in[4];
    const float* p_delta = (const float*)d_in[5];
    float* y = (float*)d_out;

    proj_kernel<<<BL/TL, 128>>>(u, W_B, W_C, q_delta, p_delta);
    scan_init_kernel<<<dim3(DIM/128, NCH, BATCH), 128>>>(u, A);
    chain_kernel<<<(BATCH*DIM*NST)/256, 256>>>(A);
    scan_main_kernel<<<dim3(DIM/128, NCH, BATCH), 128>>>(u, A, y);
}

// round 7
// speedup vs baseline: 1.0104x; 1.0104x over previous
#include <cuda_runtime.h>
#include <math.h>

#define BATCH 4
#define SEQL  2048
#define DIM   768
#define NST   16
#define BL    (BATCH*SEQL)
#define NCH   64
#define CL    (SEQL/NCH)   // 32

#define TL 64              // proj tile = 2 chunks
#define KC 32
#define LOG2E 1.4426950408889634f

// scratch (static device globals — no runtime allocation)
__device__ float g_delta[BL];
__device__ float g_sdelta[BATCH*NCH];
__device__ float g_Bt[BL*NST];   // [pos][n]
__device__ float g_Ct[BL*NST];   // [pos][n]
__device__ float g_xend [BATCH*DIM*NCH*NST];  // [(b*DIM+d)*NCH + c][n]
__device__ float g_xinit[BATCH*DIM*NCH*NST];

__device__ __forceinline__ float ex2f(float x) {
    float y;
    asm("ex2.approx.ftz.f32 %0, %1;" : "=f"(y) : "f"(x));
    return y;
}

// ---- kernel 1: proj + fused delta/softplus + chunk delta-sums ---------------
__global__ void proj_kernel(const float* __restrict__ u,
                            const float* __restrict__ W_B,
                            const float* __restrict__ W_C,
                            const float* __restrict__ q_delta,
                            const float* __restrict__ p_delta) {
    __shared__ __align__(16) float Us[KC*68];
    __shared__ __align__(16) float Ws[KC*36];   // cols 0..31 = W rows, col 32 = q_delta
    __shared__ __align__(16) float Bo[TL*NST];
    __shared__ __align__(16) float Co[TL*NST];
    int t  = threadIdx.x;       // 128 threads
    int tx = t & 15;
    int ty = t >> 4;
    int blb = blockIdx.x * TL;

    float acc[4][4];
    float dacc[4] = {0.f, 0.f, 0.f, 0.f};
#pragma unroll
    for (int a = 0; a < 4; a++)
#pragma unroll
        for (int c = 0; c < 4; c++) acc[a][c] = 0.f;

    for (int dc = 0; dc < DIM; dc += KC) {
#pragma unroll
        for (int it = 0; it < (TL*KC)/128; it++) {
            int idx = t + it*128;
            int k = idx & 31, p = idx >> 5;
            Us[k*68 + p] = u[(size_t)(blb + p)*DIM + dc + k];
        }
#pragma unroll
        for (int it = 0; it < (32*KC)/128; it++) {
            int idx = t + it*128;
            int k = idx & 31, j = idx >> 5;
            const float* wr = (j < 16) ? (W_B + j*DIM) : (W_C + (j-16)*DIM);
            Ws[k*36 + j] = wr[dc + k];
        }
        if (t < 32) Ws[t*36 + 32] = q_delta[dc + t];
        __syncthreads();
#pragma unroll
        for (int k = 0; k < KC; k++) {
            float4 u4 = *(const float4*)(Us + k*68 + tx*4);
            float4 w4 = *(const float4*)(Ws + k*36 + ty*4);
            float us[4] = {u4.x, u4.y, u4.z, u4.w};
            float ws4[4] = {w4.x, w4.y, w4.z, w4.w};
#pragma unroll
            for (int a = 0; a < 4; a++)
#pragma unroll
                for (int c = 0; c < 4; c++)
                    acc[a][c] = fmaf(ws4[a], us[c], acc[a][c]);
            if (ty == 0) {
                float qk = Ws[k*36 + 32];
#pragma unroll
                for (int c = 0; c < 4; c++)
                    dacc[c] = fmaf(qk, us[c], dacc[c]);
            }
        }
        __syncthreads();
    }
    // delta epilogue — lanes 0..15 of warp 0; tx 0-7 = chunk 2*bx, tx 8-15 = chunk 2*bx+1
    if (ty == 0) {
        float p0 = p_delta[0];
        float s = 0.f;
#pragma unroll
        for (int c = 0; c < 4; c++) {
            float z = dacc[c] + p0;
            float sp = (z > 20.f) ? z : log1pf(__expf(z));
            g_delta[blb + tx*4 + c] = sp;
            s += sp;
        }
        // 8-lane sub-reductions (groups {0-7},{8-15} independent: offsets < 8)
        s += __shfl_xor_sync(0xffffu, s, 4);
        s += __shfl_xor_sync(0xffffu, s, 2);
        s += __shfl_xor_sync(0xffffu, s, 1);
        if (tx == 0) g_sdelta[blockIdx.x*2]     = s;
        if (tx == 8) g_sdelta[blockIdx.x*2 + 1] = s;
    }
    // transpose B/C through smem to [pos][n]
#pragma unroll
    for (int a = 0; a < 4; a++) {
        int j = ty*4 + a;
        float* o = (j < 16) ? Bo : Co;
        int jj = j & 15;
#pragma unroll
        for (int c = 0; c < 4; c++)
            o[(tx*4 + c)*NST + jj] = acc[a][c];
    }
    __syncthreads();
#pragma unroll
    for (int it = 0; it < (TL*NST)/(128*4); it++) {
        int i = (t + it*128)*4;
        *(float4*)(g_Bt + (size_t)blb*NST + i) = *(const float4*)(Bo + i);
        *(float4*)(g_Ct + (size_t)blb*NST + i) = *(const float4*)(Co + i);
    }
}

// ---- kernel 2: local chunk scans (x0 = 0) -> x_end --------------------------
__global__ void __launch_bounds__(128, 8) scan_init_kernel(const float* __restrict__ u,
                                                           const float* __restrict__ A) {
    __shared__ float ds[CL];
    __shared__ __align__(16) float Bs[CL*NST];
    __shared__ __align__(16) float Uss[CL*128];
    int t = threadIdx.x;
    int b = blockIdx.z, c = blockIdx.y;
    int d0 = blockIdx.x * 128;
    int d = d0 + t;
    int pos0 = b*SEQL + c*CL;

    if (t < CL) ds[t] = g_delta[pos0 + t];
#pragma unroll
    for (int i = t; i < CL*NST/4; i += 128)
        *(float4*)(Bs + i*4) = *(const float4*)(g_Bt + (size_t)pos0*NST + i*4);
    // stage u tile [CL][128] (coalesced float4, MLP=8)
#pragma unroll
    for (int i = t; i < CL*32; i += 128) {
        int row = i >> 5, col = i & 31;
        *(float4*)(Uss + row*128 + col*4) =
            *(const float4*)(u + (size_t)(pos0 + row)*DIM + d0 + col*4);
    }
    __syncthreads();

    float A2[NST];
#pragma unroll
    for (int k = 0; k < 4; k++) {
        float4 a4 = *(const float4*)(A + d*NST + k*4);
        A2[k*4+0] = a4.x*LOG2E; A2[k*4+1] = a4.y*LOG2E;
        A2[k*4+2] = a4.z*LOG2E; A2[k*4+3] = a4.w*LOG2E;
    }
    float x[NST];
#pragma unroll
    for (int k = 0; k < NST; k++) x[k] = 0.f;

#pragma unroll 4
    for (int l = 0; l < CL; l++) {
        float dl = ds[l];
        float du = dl * Uss[l*128 + t];
        const float4* bp = (const float4*)(Bs + l*NST);
#pragma unroll
        for (int k = 0; k < 4; k++) {
            float4 b4 = bp[k];
            x[k*4+0] = fmaf(ex2f(dl*A2[k*4+0]), x[k*4+0], du*b4.x);
            x[k*4+1] = fmaf(ex2f(dl*A2[k*4+1]), x[k*4+1], du*b4.y);
            x[k*4+2] = fmaf(ex2f(dl*A2[k*4+2]), x[k*4+2], du*b4.z);
            x[k*4+3] = fmaf(ex2f(dl*A2[k*4+3]), x[k*4+3], du*b4.w);
        }
    }
    float* xe = g_xend + (((size_t)b*DIM + d)*NCH + c)*NST;
#pragma unroll
    for (int k = 0; k < 4; k++)
        *(float4*)(xe + k*4) = make_float4(x[k*4], x[k*4+1], x[k*4+2], x[k*4+3]);
}

// ---- kernel 3: serial chain over chunks -> x_init ---------------------------
__global__ void chain_kernel(const float* __restrict__ A) {
    int t = blockIdx.x * blockDim.x + threadIdx.x;   // (b*DIM+d)*NST + n
    int n = t & 15;
    int bd = t >> 4;
    int b = bd / DIM;
    int d = bd - b*DIM;
    float A2 = A[d*NST + n] * LOG2E;
    float x = 0.f;
#pragma unroll
    for (int c = 0; c < NCH; c++) {
        size_t idx = ((size_t)bd*NCH + c)*NST + n;
        g_xinit[idx] = x;
        float P = ex2f(A2 * g_sdelta[b*NCH + c]);
        x = fmaf(P, x, g_xend[idx]);
    }
}

// ---- kernel 4: main scan with correct init, emit y --------------------------
__global__ void __launch_bounds__(128, 8) scan_main_kernel(const float* __restrict__ u,
                                                           const float* __restrict__ A,
                                                           float* __restrict__ y) {
    __shared__ float ds[CL];
    __shared__ __align__(16) float Bs[CL*NST];
    __shared__ __align__(16) float Cs[CL*NST];
    __shared__ __align__(16) float Uss[CL*128];
    int t = threadIdx.x;
    int b = blockIdx.z, c = blockIdx.y;
    int d0 = blockIdx.x * 128;
    int d = d0 + t;
    int pos0 = b*SEQL + c*CL;

    if (t < CL) ds[t] = g_delta[pos0 + t];
#pragma unroll
    for (int i = t; i < CL*NST/4; i += 128) {
        *(float4*)(Bs + i*4) = *(const float4*)(g_Bt + (size_t)pos0*NST + i*4);
        *(float4*)(Cs + i*4) = *(const float4*)(g_Ct + (size_t)pos0*NST + i*4);
    }
#pragma unroll
    for (int i = t; i < CL*32; i += 128) {
        int row = i >> 5, col = i & 31;
        *(float4*)(Uss + row*128 + col*4) =
            *(const float4*)(u + (size_t)(pos0 + row)*DIM + d0 + col*4);
    }
    __syncthreads();

    float A2[NST];
#pragma unroll
    for (int k = 0; k < 4; k++) {
        float4 a4 = *(const float4*)(A + d*NST + k*4);
        A2[k*4+0] = a4.x*LOG2E; A2[k*4+1] = a4.y*LOG2E;
        A2[k*4+2] = a4.z*LOG2E; A2[k*4+3] = a4.w*LOG2E;
    }
    float x[NST];
    const float* xi = g_xinit + (((size_t)b*DIM + d)*NCH + c)*NST;
#pragma unroll
    for (int k = 0; k < 4; k++) {
        float4 v = *(const float4*)(xi + k*4);
        x[k*4] = v.x; x[k*4+1] = v.y; x[k*4+2] = v.z; x[k*4+3] = v.w;
    }

    float* yp = y + (size_t)pos0*DIM + d;
#pragma unroll 4
    for (int l = 0; l < CL; l++) {
        float dl = ds[l];
        float du = dl * Uss[l*128 + t];
        const float4* bp = (const float4*)(Bs + l*NST);
        const float4* cp = (const float4*)(Cs + l*NST);
        float acc = 0.f;
#pragma unroll
        for (int k = 0; k < 4; k++) {
            float4 b4 = bp[k];
            float4 c4 = cp[k];
            x[k*4+0] = fmaf(ex2f(dl*A2[k*4+0]), x[k*4+0], du*b4.x);
            x[k*4+1] = fmaf(ex2f(dl*A2[k*4+1]), x[k*4+1], du*b4.y);
            x[k*4+2] = fmaf(ex2f(dl*A2[k*4+2]), x[k*4+2], du*b4.z);
            x[k*4+3] = fmaf(ex2f(dl*A2[k*4+3]), x[k*4+3], du*b4.w);
            acc = fmaf(x[k*4+0], c4.x, acc);
            acc = fmaf(x[k*4+1], c4.y, acc);
            acc = fmaf(x[k*4+2], c4.z, acc);
            acc = fmaf(x[k*4+3], c4.w, acc);
        }
        yp[(size_t)l*DIM] = acc;
    }
}

extern "C" void kernel_launch(void* const* d_in, const int* in_sizes, int n_in,
                              void* d_out, int out_size) {
    const float* u       = (const float*)d_in[0];
    const float* A       = (const float*)d_in[1];
    const float* W_B     = (const float*)d_in[2];
    const float* W_C     = (const float*)d_in[3];
    const float* q_delta = (const float*)d_in[4];
    const float* p_delta = (const float*)d_in[5];
    float* y = (float*)d_out;

    proj_kernel<<<BL/TL, 128>>>(u, W_B, W_C, q_delta, p_delta);
    scan_init_kernel<<<dim3(DIM/128, NCH, BATCH), 128>>>(u, A);
    chain_kernel<<<(BATCH*DIM*NST)/256, 256>>>(A);
    scan_main_kernel<<<dim3(DIM/128, NCH, BATCH), 128>>>(u, A, y);
}

// round 8
// speedup vs baseline: 1.2277x; 1.2150x over previous
#include <cuda_runtime.h>
#include <math.h>

#define BATCH 4
#define SEQL  2048
#define DIM   768
#define NST   16
#define BL    (BATCH*SEQL)
#define NCH   32
#define CL    (SEQL/NCH)   // 64

#define TL 64              // proj tile == chunk
#define KC 32
#define LOG2E 1.4426950408889634f

// scratch (static device globals — no runtime allocation)
__device__ float g_delta[BL];
__device__ float g_sdelta[BATCH*NCH];
__device__ float g_Bt[BL*NST];   // [pos][n]
__device__ float g_Ct[BL*NST];   // [pos][n]
__device__ float g_xend [BATCH*DIM*NCH*NST];  // [(b*DIM+d)*NCH + c][n]
__device__ float g_xinit[BATCH*DIM*NCH*NST];

__device__ __forceinline__ float ex2f(float x) {
    float y;
    asm("ex2.approx.ftz.f32 %0, %1;" : "=f"(y) : "f"(x));
    return y;
}

// ---- kernel 1: proj + fused delta/softplus + chunk delta-sums ---------------
__global__ void proj_kernel(const float* __restrict__ u,
                            const float* __restrict__ W_B,
                            const float* __restrict__ W_C,
                            const float* __restrict__ q_delta,
                            const float* __restrict__ p_delta) {
    __shared__ __align__(16) float Us[KC*68];
    __shared__ __align__(16) float Ws[KC*36];   // cols 0..31 = W rows, col 32 = q_delta
    __shared__ __align__(16) float Bo[TL*NST];
    __shared__ __align__(16) float Co[TL*NST];
    int t  = threadIdx.x;       // 128 threads
    int tx = t & 15;
    int ty = t >> 4;
    int blb = blockIdx.x * TL;

    float acc[4][4];
    float dacc[4] = {0.f, 0.f, 0.f, 0.f};
#pragma unroll
    for (int a = 0; a < 4; a++)
#pragma unroll
        for (int c = 0; c < 4; c++) acc[a][c] = 0.f;

    for (int dc = 0; dc < DIM; dc += KC) {
#pragma unroll
        for (int it = 0; it < (TL*KC)/128; it++) {
            int idx = t + it*128;
            int k = idx & 31, p = idx >> 5;
            Us[k*68 + p] = u[(size_t)(blb + p)*DIM + dc + k];
        }
#pragma unroll
        for (int it = 0; it < (32*KC)/128; it++) {
            int idx = t + it*128;
            int k = idx & 31, j = idx >> 5;
            const float* wr = (j < 16) ? (W_B + j*DIM) : (W_C + (j-16)*DIM);
            Ws[k*36 + j] = wr[dc + k];
        }
        if (t < 32) Ws[t*36 + 32] = q_delta[dc + t];
        __syncthreads();
#pragma unroll
        for (int k = 0; k < KC; k++) {
            float4 u4 = *(const float4*)(Us + k*68 + tx*4);
            float4 w4 = *(const float4*)(Ws + k*36 + ty*4);
            float us[4] = {u4.x, u4.y, u4.z, u4.w};
            float ws4[4] = {w4.x, w4.y, w4.z, w4.w};
#pragma unroll
            for (int a = 0; a < 4; a++)
#pragma unroll
                for (int c = 0; c < 4; c++)
                    acc[a][c] = fmaf(ws4[a], us[c], acc[a][c]);
            if (ty == 0) {
                float qk = Ws[k*36 + 32];
#pragma unroll
                for (int c = 0; c < 4; c++)
                    dacc[c] = fmaf(qk, us[c], dacc[c]);
            }
        }
        __syncthreads();
    }
    // delta epilogue — lanes 0..15 of warp 0; one chunk per block
    if (ty == 0) {
        float p0 = p_delta[0];
        float s = 0.f;
#pragma unroll
        for (int c = 0; c < 4; c++) {
            float z = dacc[c] + p0;
            float sp = (z > 20.f) ? z : log1pf(__expf(z));
            g_delta[blb + tx*4 + c] = sp;
            s += sp;
        }
#pragma unroll
        for (int o = 8; o; o >>= 1) s += __shfl_xor_sync(0xffffu, s, o);
        if (tx == 0) g_sdelta[blockIdx.x] = s;   // blockIdx.x == b*NCH + c
    }
    // transpose B/C through smem to [pos][n]
#pragma unroll
    for (int a = 0; a < 4; a++) {
        int j = ty*4 + a;
        float* o = (j < 16) ? Bo : Co;
        int jj = j & 15;
#pragma unroll
        for (int c = 0; c < 4; c++)
            o[(tx*4 + c)*NST + jj] = acc[a][c];
    }
    __syncthreads();
#pragma unroll
    for (int it = 0; it < (TL*NST)/(128*4); it++) {
        int i = (t + it*128)*4;
        *(float4*)(g_Bt + (size_t)blb*NST + i) = *(const float4*)(Bo + i);
        *(float4*)(g_Ct + (size_t)blb*NST + i) = *(const float4*)(Co + i);
    }
}

// ---- kernel 2: local chunk scans (x0 = 0) -> x_end --------------------------
__global__ void __launch_bounds__(128, 5) scan_init_kernel(const float* __restrict__ u,
                                                           const float* __restrict__ A) {
    __shared__ float ds[CL];
    __shared__ __align__(16) float Bs[CL*NST];
    __shared__ __align__(16) float Uss[CL*128];
    int t = threadIdx.x;
    int b = blockIdx.z, c = blockIdx.y;
    int d0 = blockIdx.x * 128;
    int d = d0 + t;
    int pos0 = b*SEQL + c*CL;

    if (t < CL) ds[t] = g_delta[pos0 + t];
#pragma unroll
    for (int i = t; i < CL*NST/4; i += 128)
        *(float4*)(Bs + i*4) = *(const float4*)(g_Bt + (size_t)pos0*NST + i*4);
    // stage u tile [CL][128] (coalesced float4, MLP=8)
#pragma unroll
    for (int i = t; i < CL*32; i += 128) {
        int row = i >> 5, col = i & 31;
        *(float4*)(Uss + row*128 + col*4) =
            *(const float4*)(u + (size_t)(pos0 + row)*DIM + d0 + col*4);
    }
    __syncthreads();

    float A2[NST];
#pragma unroll
    for (int k = 0; k < 4; k++) {
        float4 a4 = *(const float4*)(A + d*NST + k*4);
        A2[k*4+0] = a4.x*LOG2E; A2[k*4+1] = a4.y*LOG2E;
        A2[k*4+2] = a4.z*LOG2E; A2[k*4+3] = a4.w*LOG2E;
    }
    float x[NST];
#pragma unroll
    for (int k = 0; k < NST; k++) x[k] = 0.f;

#pragma unroll 4
    for (int l = 0; l < CL; l++) {
        float dl = ds[l];
        float du = dl * Uss[l*128 + t];
        const float4* bp = (const float4*)(Bs + l*NST);
#pragma unroll
        for (int k = 0; k < 4; k++) {
            float4 b4 = bp[k];
            x[k*4+0] = fmaf(ex2f(dl*A2[k*4+0]), x[k*4+0], du*b4.x);
            x[k*4+1] = fmaf(ex2f(dl*A2[k*4+1]), x[k*4+1], du*b4.y);
            x[k*4+2] = fmaf(ex2f(dl*A2[k*4+2]), x[k*4+2], du*b4.z);
            x[k*4+3] = fmaf(ex2f(dl*A2[k*4+3]), x[k*4+3], du*b4.w);
        }
    }
    float* xe = g_xend + (((size_t)b*DIM + d)*NCH + c)*NST;
#pragma unroll
    for (int k = 0; k < 4; k++)
        *(float4*)(xe + k*4) = make_float4(x[k*4], x[k*4+1], x[k*4+2], x[k*4+3]);
}

// ---- kernel 3: serial chain over chunks -> x_init ---------------------------
__global__ void chain_kernel(const float* __restrict__ A) {
    int t = blockIdx.x * blockDim.x + threadIdx.x;   // (b*DIM+d)*NST + n
    int n = t & 15;
    int bd = t >> 4;
    int b = bd / DIM;
    int d = bd - b*DIM;
    float A2 = A[d*NST + n] * LOG2E;
    float x = 0.f;
#pragma unroll
    for (int c = 0; c < NCH; c++) {
        size_t idx = ((size_t)bd*NCH + c)*NST + n;
        g_xinit[idx] = x;
        float P = ex2f(A2 * g_sdelta[b*NCH + c]);
        x = fmaf(P, x, g_xend[idx]);
    }
}

// ---- kernel 4: main scan with correct init, emit y --------------------------
__global__ void __launch_bounds__(128, 5) scan_main_kernel(const float* __restrict__ u,
                                                           const float* __restrict__ A,
                                                           float* __restrict__ y) {
    __shared__ float ds[CL];
    __shared__ __align__(16) float Bs[CL*NST];
    __shared__ __align__(16) float Cs[CL*NST];
    __shared__ __align__(16) float Uss[CL*128];
    int t = threadIdx.x;
    int b = blockIdx.z, c = blockIdx.y;
    int d0 = blockIdx.x * 128;
    int d = d0 + t;
    int pos0 = b*SEQL + c*CL;

    if (t < CL) ds[t] = g_delta[pos0 + t];
#pragma unroll
    for (int i = t; i < CL*NST/4; i += 128) {
        *(float4*)(Bs + i*4) = *(const float4*)(g_Bt + (size_t)pos0*NST + i*4);
        *(float4*)(Cs + i*4) = *(const float4*)(g_Ct + (size_t)pos0*NST + i*4);
    }
#pragma unroll
    for (int i = t; i < CL*32; i += 128) {
        int row = i >> 5, col = i & 31;
        *(float4*)(Uss + row*128 + col*4) =
            *(const float4*)(u + (size_t)(pos0 + row)*DIM + d0 + col*4);
    }
    __syncthreads();

    float A2[NST];
#pragma unroll
    for (int k = 0; k < 4; k++) {
        float4 a4 = *(const float4*)(A + d*NST + k*4);
        A2[k*4+0] = a4.x*LOG2E; A2[k*4+1] = a4.y*LOG2E;
        A2[k*4+2] = a4.z*LOG2E; A2[k*4+3] = a4.w*LOG2E;
    }
    float x[NST];
    const float* xi = g_xinit + (((size_t)b*DIM + d)*NCH + c)*NST;
#pragma unroll
    for (int k = 0; k < 4; k++) {
        float4 v = *(const float4*)(xi + k*4);
        x[k*4] = v.x; x[k*4+1] = v.y; x[k*4+2] = v.z; x[k*4+3] = v.w;
    }

    float* yp = y + (size_t)pos0*DIM + d;
#pragma unroll 4
    for (int l = 0; l < CL; l++) {
        float dl = ds[l];
        float du = dl * Uss[l*128 + t];
        const float4* bp = (const float4*)(Bs + l*NST);
        const float4* cp = (const float4*)(Cs + l*NST);
        float acc = 0.f;
#pragma unroll
        for (int k = 0; k < 4; k++) {
            float4 b4 = bp[k];
            float4 c4 = cp[k];
            x[k*4+0] = fmaf(ex2f(dl*A2[k*4+0]), x[k*4+0], du*b4.x);
            x[k*4+1] = fmaf(ex2f(dl*A2[k*4+1]), x[k*4+1], du*b4.y);
            x[k*4+2] = fmaf(ex2f(dl*A2[k*4+2]), x[k*4+2], du*b4.z);
            x[k*4+3] = fmaf(ex2f(dl*A2[k*4+3]), x[k*4+3], du*b4.w);
            acc = fmaf(x[k*4+0], c4.x, acc);
            acc = fmaf(x[k*4+1], c4.y, acc);
            acc = fmaf(x[k*4+2], c4.z, acc);
            acc = fmaf(x[k*4+3], c4.w, acc);
        }
        yp[(size_t)l*DIM] = acc;
    }
}

extern "C" void kernel_launch(void* const* d_in, const int* in_sizes, int n_in,
                              void* d_out, int out_size) {
    const float* u       = (const float*)d_in[0];
    const float* A       = (const float*)d_in[1];
    const float* W_B     = (const float*)d_in[2];
    const float* W_C     = (const float*)d_in[3];
    const float* q_delta = (const float*)d_in[4];
    const float* p_delta = (const float*)d_in[5];
    float* y = (float*)d_out;

    proj_kernel<<<BL/TL, 128>>>(u, W_B, W_C, q_delta, p_delta);
    scan_init_kernel<<<dim3(DIM/128, NCH, BATCH), 128>>>(u, A);
    chain_kernel<<<(BATCH*DIM*NST)/256, 256>>>(A);
    scan_main_kernel<<<dim3(DIM/128, NCH, BATCH), 128>>>(u, A, y);
}